// round 13
// baseline (speedup 1.0000x reference)
#include <cuda_runtime.h>
#include <cuda_bf16.h>
#include <stdint.h>

#define D       512
#define NB      512
#define NM      65536
#define BT      128
#define MT      128
#define KT      32                 // k per stage
#define NSTG    (D / KT)           // 16
#define ROWF    144                // fp32 stage row stride (128 B payload + 16 pad)
#define FAB     (128 * ROWF)       // 18432 per fp32 tile array
#define FSTG    (2 * FAB)          // 36864 per fp32 stage (A+B)
#define ROWB    80                 // bf16 row stride (R6-proven conflict-free)
#define ABYTES  (128 * ROWB)       // 10240 per bf16 tile array
#define BSTG    (2 * ABYTES)       // 20480 per bf16 buffer (A+B)
#define BBASE   (2 * FSTG)         // 73728: bf16 double-buffer base
#define SMEM_DYN (BBASE + 2 * BSTG) // 114688 -> 2 CTA/SM
#define NTILES  (NM / MT)          // 512
#define NGRP    (NM / 8)           // 8192
#define DELTA   0.09f

// ---------------- device scratch (allocation-free rule) ----------------
__device__ float g_inv_norm[NM];
__device__ float g_subbest[NB * NGRP];      // per (query, 8-row m-group) screen max

// ---------------- helpers ----------------
__device__ __forceinline__ unsigned int f2mono(float f) {
    unsigned int b = __float_as_uint(f);
    return (b & 0x80000000u) ? ~b : (b | 0x80000000u);
}
__device__ __forceinline__ uint32_t s2u(const void* p) {
    return (uint32_t)__cvta_generic_to_shared(p);
}
__device__ __forceinline__ void cp16(uint32_t dst, const void* src) {
    asm volatile("cp.async.cg.shared.global [%0], [%1], 16;" :: "r"(dst), "l"(src));
}
__device__ __forceinline__ void ldm_x4(uint32_t& r0, uint32_t& r1, uint32_t& r2, uint32_t& r3, uint32_t a) {
    asm volatile("ldmatrix.sync.aligned.m8n8.x4.shared.b16 {%0,%1,%2,%3}, [%4];"
                 : "=r"(r0), "=r"(r1), "=r"(r2), "=r"(r3) : "r"(a));
}
__device__ __forceinline__ void mma16816(float* c, const uint32_t* a, const uint32_t* b) {
    asm volatile("mma.sync.aligned.m16n8k16.row.col.f32.bf16.bf16.f32 "
                 "{%0,%1,%2,%3}, {%4,%5,%6,%7}, {%8,%9}, {%0,%1,%2,%3};"
                 : "+f"(c[0]), "+f"(c[1]), "+f"(c[2]), "+f"(c[3])
                 : "r"(a[0]), "r"(a[1]), "r"(a[2]), "r"(a[3]), "r"(b[0]), "r"(b[1]));
}
__device__ __forceinline__ uint32_t pk(float a, float b) {
    __nv_bfloat162 t = __floats2bfloat162_rn(a, b);
    return *(uint32_t*)&t;
}

// ---------------- fused GEMM: fp32 in, inline bf16 convert + norms + screen max ----------------
// grid: (512 m-tiles [fastest], 4 b-tiles). 256 threads = 8 warps, warp = 64b x 32m.
// fp32 staging: 2 buffers (thread-private slots -> no extra sync).
// bf16 staging: 2 buffers, guarded by the per-stage __syncthreads.
__global__ __launch_bounds__(256) void gemm_kernel(const float* __restrict__ ctx,
                                                   const float* __restrict__ mem) {
    extern __shared__ __align__(128) char dsm[];
    __shared__ float ssqh[2][128];
    __shared__ float sinv[128];

    const int tid = threadIdx.x, lane = tid & 31, w = tid >> 5;
    const int wb = w >> 2, wm = w & 3;
    const int mtile = blockIdx.x;
    const int b0 = blockIdx.y * BT;

    const int row = tid >> 1;                 // 0..127: loader/converter row
    const int half = tid & 1;                 // 64-byte half of the 128B fp32 row
    const char* aF = (const char*)(ctx + (size_t)(b0 + row) * D) + half * 64;
    const char* bF = (const char*)(mem + (size_t)(mtile * MT + row) * D) + half * 64;
    const uint32_t smbase = s2u(dsm);
    const uint32_t fdstA = smbase + row * ROWF + half * 64;   // + (s&1)*FSTG
    const uint32_t bobase = row * ROWB + half * 32;           // + BBASE + (s&1)*BSTG (+ABYTES for B)

    float acc[4][4][4];
#pragma unroll
    for (int i = 0; i < 4; i++)
#pragma unroll
        for (int j = 0; j < 4; j++)
#pragma unroll
            for (int k = 0; k < 4; k++) acc[i][j][k] = 0.f;

    const uint32_t aoff = (uint32_t)(BBASE + (wb * 64 + (lane & 15)) * ROWB + (lane >> 4) * 16);
    const uint32_t boff = (uint32_t)(BBASE + ABYTES + (wm * 32 + (lane >> 4) * 8 + (lane & 7)) * ROWB + ((lane >> 3) & 1) * 16);

    float ssq = 0.f;   // sum of squares of this thread's memory half-row (fp32-exact)

    auto load_f = [&](int s) {
        uint32_t off = (uint32_t)((s & 1) * FSTG);
        const char* a = aF + s * 128;
        const char* b = bF + s * 128;
        cp16(fdstA + off,      a);       cp16(fdstA + off + 16, a + 16);
        cp16(fdstA + off + 32, a + 32);  cp16(fdstA + off + 48, a + 48);
        cp16(fdstA + off + FAB,      b);      cp16(fdstA + off + FAB + 16, b + 16);
        cp16(fdstA + off + FAB + 32, b + 32); cp16(fdstA + off + FAB + 48, b + 48);
        asm volatile("cp.async.commit_group;" ::: "memory");
    };

    auto convert = [&](int s) {
        const char* fb = dsm + (s & 1) * FSTG + row * ROWF + half * 64;
        char* bb = dsm + BBASE + (s & 1) * BSTG + bobase;
        // A: ctx fp32 -> bf16
        {
            float4 x0 = *(const float4*)(fb);
            float4 x1 = *(const float4*)(fb + 16);
            float4 x2 = *(const float4*)(fb + 32);
            float4 x3 = *(const float4*)(fb + 48);
            *(uint4*)(bb)      = make_uint4(pk(x0.x, x0.y), pk(x0.z, x0.w), pk(x1.x, x1.y), pk(x1.z, x1.w));
            *(uint4*)(bb + 16) = make_uint4(pk(x2.x, x2.y), pk(x2.z, x2.w), pk(x3.x, x3.y), pk(x3.z, x3.w));
        }
        // B: mem fp32 -> bf16 (+ norm accumulation)
        {
            float4 x0 = *(const float4*)(fb + FAB);
            float4 x1 = *(const float4*)(fb + FAB + 16);
            float4 x2 = *(const float4*)(fb + FAB + 32);
            float4 x3 = *(const float4*)(fb + FAB + 48);
            ssq += x0.x * x0.x + x0.y * x0.y + x0.z * x0.z + x0.w * x0.w;
            ssq += x1.x * x1.x + x1.y * x1.y + x1.z * x1.z + x1.w * x1.w;
            ssq += x2.x * x2.x + x2.y * x2.y + x2.z * x2.z + x2.w * x2.w;
            ssq += x3.x * x3.x + x3.y * x3.y + x3.z * x3.z + x3.w * x3.w;
            *(uint4*)(bb + ABYTES)      = make_uint4(pk(x0.x, x0.y), pk(x0.z, x0.w), pk(x1.x, x1.y), pk(x1.z, x1.w));
            *(uint4*)(bb + ABYTES + 16) = make_uint4(pk(x2.x, x2.y), pk(x2.z, x2.w), pk(x3.x, x3.y), pk(x3.z, x3.w));
        }
    };

    // prologue: fp32 stages 0,1 in flight; convert stage 0 (thread-private wait)
    load_f(0); load_f(1);
    asm volatile("cp.async.wait_group 1;" ::: "memory");
    convert(0);

    for (int s = 0; s < NSTG; s++) {
        __syncthreads();   // all warps done: mma(s-1) reads, convert(s) writes
        if (s + 2 < NSTG) load_f(s + 2);
        if (s < NSTG - 1) {
            if (s + 2 < NSTG) asm volatile("cp.async.wait_group 1;" ::: "memory");
            else              asm volatile("cp.async.wait_group 0;" ::: "memory");
            convert(s + 1);
        }
        // mma on stage s (bf16 buffer s&1, written by convert(s) last iteration)
        uint32_t sb = smbase + (uint32_t)((s & 1) * BSTG);
#pragma unroll
        for (int h = 0; h < 2; h++) {
            uint32_t afr[4][4], bfr[2][4];
#pragma unroll
            for (int i = 0; i < 4; i++)
                ldm_x4(afr[i][0], afr[i][1], afr[i][2], afr[i][3],
                       sb + aoff + (uint32_t)(i * 16 * ROWB + h * 32));
#pragma unroll
            for (int p = 0; p < 2; p++)
                ldm_x4(bfr[p][0], bfr[p][1], bfr[p][2], bfr[p][3],
                       sb + boff + (uint32_t)(p * 16 * ROWB + h * 32));
#pragma unroll
            for (int i = 0; i < 4; i++)
#pragma unroll
                for (int j = 0; j < 4; j++)
                    mma16816(acc[i][j], afr[i], &bfr[j >> 1][(j & 1) * 2]);
        }
    }

    // finalize norms (fp32-exact, same definition as reference)
    ssqh[half][row] = ssq;
    __syncthreads();
    if (tid < 128) {
        float t = ssqh[0][tid] + ssqh[1][tid];
        float iv = rsqrtf(fmaxf(t, 1e-12f));
        sinv[tid] = iv;
        if (blockIdx.y == 0) g_inv_norm[mtile * MT + tid] = iv;
    }
    __syncthreads();

    // epilogue: scale by per-column inv_norm, per-(query row, 8-col group) max
    float (*sg)[16] = (float(*)[16])dsm;   // overlays fp32 buf0 (fully consumed)
#pragma unroll
    for (int i = 0; i < 4; i++)
#pragma unroll
        for (int j = 0; j < 4; j++) {
            int col0 = wm * 32 + j * 8 + 2 * (lane & 3);
            float sv0 = sinv[col0], sv1 = sinv[col0 + 1];
            float p0 = fmaxf(acc[i][j][0] * sv0, acc[i][j][1] * sv1);
            float p1 = fmaxf(acc[i][j][2] * sv0, acc[i][j][3] * sv1);
            p0 = fmaxf(p0, __shfl_xor_sync(0xffffffffu, p0, 1));
            p0 = fmaxf(p0, __shfl_xor_sync(0xffffffffu, p0, 2));
            p1 = fmaxf(p1, __shfl_xor_sync(0xffffffffu, p1, 1));
            p1 = fmaxf(p1, __shfl_xor_sync(0xffffffffu, p1, 2));
            if ((lane & 3) == 0) {
                int r = wb * 64 + i * 16 + (lane >> 2);
                sg[r][wm * 4 + j] = p0;
                sg[r + 8][wm * 4 + j] = p1;
            }
        }
    __syncthreads();
    {
        int r = tid >> 1, hf = tid & 1;
        float* dst = &g_subbest[(size_t)(b0 + r) * NGRP + mtile * 16 + hf * 8];
        const float* src = &sg[r][hf * 8];
        *(float4*)dst = *(const float4*)src;
        *(float4*)(dst + 4) = *(const float4*)(src + 4);
    }
}

// ---------------- rescue + gather fused (unchanged, R12-proven) ----------------
__global__ __launch_bounds__(256) void rescue_kernel(const float* __restrict__ ctx,
                                                     const float* __restrict__ mem,
                                                     float* __restrict__ out) {
    __shared__ __align__(16) float sb[NGRP];     // 32 KB
    __shared__ __align__(16) float cs[D];
    __shared__ float sred[8];
    __shared__ float sthresh;
    __shared__ int clist[1024];
    __shared__ int ccount;
    __shared__ unsigned long long wkey[8];
    __shared__ int sbest;

    const int b = blockIdx.x, tid = threadIdx.x, wid = tid >> 5, lane = tid & 31;

    cs[tid] = ctx[(size_t)b * D + tid];
    cs[tid + 256] = ctx[(size_t)b * D + tid + 256];
    if (tid == 0) ccount = 0;

    float vmax = -3.4e38f;
    const float4* gsrc = (const float4*)&g_subbest[(size_t)b * NGRP];
#pragma unroll
    for (int i = 0; i < NGRP / 4 / 256; i++) {
        float4 v = gsrc[tid + i * 256];
        *(float4*)&sb[(tid + i * 256) * 4] = v;
        vmax = fmaxf(vmax, fmaxf(fmaxf(v.x, v.y), fmaxf(v.z, v.w)));
    }
#pragma unroll
    for (int o = 16; o > 0; o >>= 1) vmax = fmaxf(vmax, __shfl_xor_sync(0xffffffffu, vmax, o));
    if (lane == 0) sred[wid] = vmax;
    __syncthreads();
    if (tid == 0) {
        float m = sred[0];
#pragma unroll
        for (int i = 1; i < 8; i++) m = fmaxf(m, sred[i]);
        sthresh = m - DELTA;
    }
    __syncthreads();
    const float thresh = sthresh;

    for (int g = tid; g < NGRP; g += 256) {
        if (sb[g] >= thresh) {
            int pos = atomicAdd(&ccount, 1);
            if (pos < 1024) clist[pos] = g;
        }
    }
    __syncthreads();
    int nc = ccount; if (nc > 1024) nc = 1024;

    unsigned long long best = 0ull;
    for (int ci = wid; ci < nc; ci += 8) {
        int g = clist[ci];
#pragma unroll
        for (int r = 0; r < 8; r++) {
            int m = g * 8 + r;
            const float4* mr = (const float4*)(mem + (size_t)m * D);
            float s = 0.f;
#pragma unroll
            for (int i = 0; i < 4; i++) {
                float4 q = mr[lane + i * 32];
                float4 c = *(const float4*)&cs[(lane + i * 32) * 4];
                s = fmaf(q.x, c.x, s); s = fmaf(q.y, c.y, s);
                s = fmaf(q.z, c.z, s); s = fmaf(q.w, c.w, s);
            }
#pragma unroll
            for (int o = 16; o > 0; o >>= 1) s += __shfl_xor_sync(0xffffffffu, s, o);
            s *= g_inv_norm[m];
            unsigned long long key = ((unsigned long long)f2mono(s) << 32) |
                                     (unsigned long long)(0xFFFFFFFFu - (unsigned)m);
            if (key > best) best = key;
        }
    }
#pragma unroll
    for (int o = 16; o > 0; o >>= 1) {
        unsigned long long ok = __shfl_xor_sync(0xffffffffu, best, o);
        if (ok > best) best = ok;
    }
    if (lane == 0) wkey[wid] = best;
    __syncthreads();
    if (tid == 0) {
        unsigned long long k = wkey[0];
#pragma unroll
        for (int i = 1; i < 8; i++) if (wkey[i] > k) k = wkey[i];
        sbest = (int)(0xFFFFFFFFu - (unsigned)(k & 0xFFFFFFFFull));
    }
    __syncthreads();

    const int idx = sbest;
    const float4* src = (const float4*)(mem + (size_t)idx * D);
    float4* dst = (float4*)(out + (size_t)b * D);
    if (tid < D / 4) dst[tid] = src[tid];
}

// ---------------- launch ----------------
extern "C" void kernel_launch(void* const* d_in, const int* in_sizes, int n_in,
                              void* d_out, int out_size)
{
    const float* ctx = (const float*)d_in[0];   // [512, 512] f32
    const float* mem = (const float*)d_in[1];   // [65536, 512] f32
    float* out = (float*)d_out;                 // [1, 512, 512] f32

    cudaFuncSetAttribute(gemm_kernel, cudaFuncAttributeMaxDynamicSharedMemorySize, SMEM_DYN);

    gemm_kernel<<<dim3(NTILES, NB / BT), 256, SMEM_DYN>>>(ctx, mem);
    rescue_kernel<<<NB, 256>>>(ctx, mem, out);
}

// round 15
// speedup vs baseline: 2.0560x; 2.0560x over previous
#include <cuda_runtime.h>
#include <cuda_bf16.h>
#include <stdint.h>

#define D       512
#define NB      512
#define NM      65536
#define BT      128
#define MT      128
#define KT      32                 // k per pipeline stage (bf16 elems)
#define NSTG    (D / KT)           // 16
#define ROWB    80                 // padded smem row stride (bytes) -> conflict-free
#define ABYTES  (128 * ROWB)       // 10240 per tile array
#define STGB    (2 * ABYTES)       // 20480 per stage (A+B)
#define NBUF    4
#define SMEM_DYN (NBUF * STGB)     // 81920
#define NTILES  (NM / MT)          // 512
#define NGRP    (NM / 8)           // 8192 8-row groups
#define DELTA   0.09f

// ---------------- device scratch (allocation-free rule) ----------------
__device__ __nv_bfloat16 g_mem_b[NM * D];   // normalized memory, bf16 row-major
__device__ __nv_bfloat16 g_ctx_b[NB * D];   // context, bf16 row-major
__device__ float g_inv_norm[NM];
__device__ __nv_bfloat16 g_subbest[NB * NGRP];  // per (query, 8-row m-group) screen max (bf16)

// ---------------- helpers ----------------
__device__ __forceinline__ unsigned int f2mono(float f) {
    unsigned int b = __float_as_uint(f);
    return (b & 0x80000000u) ? ~b : (b | 0x80000000u);
}
__device__ __forceinline__ uint32_t s2u(const void* p) {
    return (uint32_t)__cvta_generic_to_shared(p);
}
__device__ __forceinline__ void cp16(uint32_t dst, const void* src) {
    asm volatile("cp.async.cg.shared.global [%0], [%1], 16;" :: "r"(dst), "l"(src));
}
__device__ __forceinline__ void ldm_x4(uint32_t& r0, uint32_t& r1, uint32_t& r2, uint32_t& r3, uint32_t a) {
    asm volatile("ldmatrix.sync.aligned.m8n8.x4.shared.b16 {%0,%1,%2,%3}, [%4];"
                 : "=r"(r0), "=r"(r1), "=r"(r2), "=r"(r3) : "r"(a));
}
__device__ __forceinline__ void mma16816(float* c, const uint32_t* a, const uint32_t* b) {
    asm volatile("mma.sync.aligned.m16n8k16.row.col.f32.bf16.bf16.f32 "
                 "{%0,%1,%2,%3}, {%4,%5,%6,%7}, {%8,%9}, {%0,%1,%2,%3};"
                 : "+f"(c[0]), "+f"(c[1]), "+f"(c[2]), "+f"(c[3])
                 : "r"(a[0]), "r"(a[1]), "r"(a[2]), "r"(a[3]), "r"(b[0]), "r"(b[1]));
}
__device__ __forceinline__ uint32_t pk(float a, float b) {
    __nv_bfloat162 t = __floats2bfloat162_rn(a, b);
    return *(uint32_t*)&t;
}

// ---------------- 1) convert fp32 -> bf16 (both tensors, one launch) ----------------
// rows [0, NM): memory (normalized); rows [NM, NM+NB): context.
__global__ __launch_bounds__(256) void convert_kernel(const float* __restrict__ mem,
                                                      const float* __restrict__ ctx) {
    int row = blockIdx.x * 8 + (threadIdx.x >> 5);
    int lane = threadIdx.x & 31;
    const int is_mem = row < NM;
    const float* src = is_mem ? (mem + (size_t)row * D)
                              : (ctx + (size_t)(row - NM) * D);
    const float4* rp = (const float4*)src;
    float4 v[4];
    float ssq = 0.f;
#pragma unroll
    for (int i = 0; i < 4; i++) {
        v[i] = rp[lane * 4 + i];
        ssq += v[i].x * v[i].x + v[i].y * v[i].y + v[i].z * v[i].z + v[i].w * v[i].w;
    }
    float invn = 1.0f;
    if (is_mem) {
#pragma unroll
        for (int o = 16; o > 0; o >>= 1) ssq += __shfl_xor_sync(0xffffffffu, ssq, o);
        invn = rsqrtf(fmaxf(ssq, 1e-12f));
        if (lane == 0) g_inv_norm[row] = invn;
    }
    unsigned short h[16];
    const float* vs = (const float*)v;
#pragma unroll
    for (int i = 0; i < 16; i++)
        h[i] = __bfloat16_as_ushort(__float2bfloat16_rn(vs[i] * invn));
    __nv_bfloat16* dst = (is_mem ? (g_mem_b + (size_t)row * D)
                                 : (g_ctx_b + (size_t)(row - NM) * D)) + lane * 16;
#pragma unroll
    for (int g = 0; g < 2; g++) {
        uint4 w;
        w.x = ((uint32_t)h[g * 8 + 1] << 16) | h[g * 8 + 0];
        w.y = ((uint32_t)h[g * 8 + 3] << 16) | h[g * 8 + 2];
        w.z = ((uint32_t)h[g * 8 + 5] << 16) | h[g * 8 + 4];
        w.w = ((uint32_t)h[g * 8 + 7] << 16) | h[g * 8 + 6];
        *(uint4*)(dst + g * 8) = w;
    }
}

// ---------------- 2) HMMA GEMM + per-(query, 8-m-group) max  (R6/R12-proven core) ----------------
// grid: (4 b-tiles [fastest, L2 m-tile sharing], 512 m-tiles). 256 threads = 8 warps.
__global__ __launch_bounds__(256) void gemm_kernel() {
    extern __shared__ __align__(128) char dsm[];

    const int tid = threadIdx.x, lane = tid & 31, w = tid >> 5;
    const int wb = w >> 2, wm = w & 3;           // warp b-half, warp m-quarter
    const int mtile = blockIdx.y;
    const int b0 = blockIdx.x * BT;

    const int arow = tid >> 1;
    const int ac = (tid & 1) * 32;
    const char* asrc = (const char*)(g_ctx_b + (size_t)(b0 + arow) * D) + ac;
    const char* bsrc = (const char*)(g_mem_b + (size_t)(mtile * MT + arow) * D) + ac;
    const uint32_t smbase = s2u(dsm);
    const uint32_t adst = smbase + arow * ROWB + ac;

    float acc[4][4][4];
#pragma unroll
    for (int i = 0; i < 4; i++)
#pragma unroll
        for (int j = 0; j < 4; j++)
#pragma unroll
            for (int k = 0; k < 4; k++) acc[i][j][k] = 0.f;

    const uint32_t aoff = (uint32_t)((wb * 64 + (lane & 15)) * ROWB + (lane >> 4) * 16);
    const uint32_t boff = (uint32_t)(ABYTES + (wm * 32 + (lane >> 4) * 8 + (lane & 7)) * ROWB + ((lane >> 3) & 1) * 16);

    auto load_stage = [&](int s) {
        uint32_t off = (uint32_t)((s & (NBUF - 1)) * STGB);
        const char* a = asrc + s * 64;
        const char* b = bsrc + s * 64;
        cp16(adst + off, a);              cp16(adst + off + 16, a + 16);
        cp16(adst + off + ABYTES, b);     cp16(adst + off + ABYTES + 16, b + 16);
        asm volatile("cp.async.commit_group;" ::: "memory");
    };

    load_stage(0); load_stage(1); load_stage(2);

    for (int s = 0; s < NSTG; s++) {
        if (s < NSTG - 2)       asm volatile("cp.async.wait_group 2;" ::: "memory");
        else if (s == NSTG - 2) asm volatile("cp.async.wait_group 1;" ::: "memory");
        else                    asm volatile("cp.async.wait_group 0;" ::: "memory");
        __syncthreads();
        if (s + 3 < NSTG) load_stage(s + 3);

        uint32_t sb = smbase + (uint32_t)((s & (NBUF - 1)) * STGB);
#pragma unroll
        for (int h = 0; h < 2; h++) {
            uint32_t afr[4][4], bfr[2][4];
#pragma unroll
            for (int i = 0; i < 4; i++)
                ldm_x4(afr[i][0], afr[i][1], afr[i][2], afr[i][3],
                       sb + aoff + (uint32_t)(i * 16 * ROWB + h * 32));
#pragma unroll
            for (int p = 0; p < 2; p++)
                ldm_x4(bfr[p][0], bfr[p][1], bfr[p][2], bfr[p][3],
                       sb + boff + (uint32_t)(p * 16 * ROWB + h * 32));
#pragma unroll
            for (int i = 0; i < 4; i++)
#pragma unroll
                for (int j = 0; j < 4; j++)
                    mma16816(acc[i][j], afr[i], &bfr[j >> 1][(j & 1) * 2]);
        }
    }

    // epilogue: per-(query row, 8-col mma group) max -> g_subbest (bf16)
    float (*sg)[16] = (float(*)[16])dsm;
#pragma unroll
    for (int i = 0; i < 4; i++)
#pragma unroll
        for (int j = 0; j < 4; j++) {
            float p0 = fmaxf(acc[i][j][0], acc[i][j][1]);
            float p1 = fmaxf(acc[i][j][2], acc[i][j][3]);
            p0 = fmaxf(p0, __shfl_xor_sync(0xffffffffu, p0, 1));
            p0 = fmaxf(p0, __shfl_xor_sync(0xffffffffu, p0, 2));
            p1 = fmaxf(p1, __shfl_xor_sync(0xffffffffu, p1, 1));
            p1 = fmaxf(p1, __shfl_xor_sync(0xffffffffu, p1, 2));
            if ((lane & 3) == 0) {
                int r = wb * 64 + i * 16 + (lane >> 2);
                sg[r][wm * 4 + j] = p0;
                sg[r + 8][wm * 4 + j] = p1;
            }
        }
    __syncthreads();
    {   // thread t: row t>>1, half t&1 -> 8 floats packed to 8 bf16 (16B store)
        int r = tid >> 1, half = tid & 1;
        const float* src = &sg[r][half * 8];
        uint4 wv = make_uint4(pk(src[0], src[1]), pk(src[2], src[3]),
                              pk(src[4], src[5]), pk(src[6], src[7]));
        *(uint4*)&g_subbest[(size_t)(b0 + r) * NGRP + mtile * 16 + half * 8] = wv;
    }
}

// ---------------- 3) rescue + gather fused ----------------
__global__ __launch_bounds__(256) void rescue_kernel(const float* __restrict__ ctx,
                                                     const float* __restrict__ mem,
                                                     float* __restrict__ out) {
    __shared__ __align__(16) float sb[NGRP];     // 32 KB (expanded fp32)
    __shared__ __align__(16) float cs[D];
    __shared__ float sred[8];
    __shared__ float sthresh;
    __shared__ int clist[1024];
    __shared__ int ccount;
    __shared__ unsigned long long wkey[8];
    __shared__ int sbest;

    const int b = blockIdx.x, tid = threadIdx.x, wid = tid >> 5, lane = tid & 31;

    cs[tid] = ctx[(size_t)b * D + tid];
    cs[tid + 256] = ctx[(size_t)b * D + tid + 256];
    if (tid == 0) ccount = 0;

    // load 8192 bf16 group maxes (16 KB), expand to fp32 smem, running max
    float vmax = -3.4e38f;
    const uint4* gsrc = (const uint4*)&g_subbest[(size_t)b * NGRP];
#pragma unroll
    for (int i = 0; i < NGRP / 8 / 256; i++) {   // 4 iters, 8 bf16 per thread
        uint4 v = gsrc[tid + i * 256];
        int base = (tid + i * 256) * 8;
        float2 f0 = __bfloat1622float2(*(__nv_bfloat162*)&v.x);
        float2 f1 = __bfloat1622float2(*(__nv_bfloat162*)&v.y);
        float2 f2 = __bfloat1622float2(*(__nv_bfloat162*)&v.z);
        float2 f3 = __bfloat1622float2(*(__nv_bfloat162*)&v.w);
        *(float4*)&sb[base]     = make_float4(f0.x, f0.y, f1.x, f1.y);
        *(float4*)&sb[base + 4] = make_float4(f2.x, f2.y, f3.x, f3.y);
        vmax = fmaxf(vmax, fmaxf(fmaxf(f0.x, f0.y), fmaxf(f1.x, f1.y)));
        vmax = fmaxf(vmax, fmaxf(fmaxf(f2.x, f2.y), fmaxf(f3.x, f3.y)));
    }
#pragma unroll
    for (int o = 16; o > 0; o >>= 1) vmax = fmaxf(vmax, __shfl_xor_sync(0xffffffffu, vmax, o));
    if (lane == 0) sred[wid] = vmax;
    __syncthreads();
    if (tid == 0) {
        float m = sred[0];
#pragma unroll
        for (int i = 1; i < 8; i++) m = fmaxf(m, sred[i]);
        sthresh = m - DELTA;
    }
    __syncthreads();
    const float thresh = sthresh;

    for (int g = tid; g < NGRP; g += 256) {
        if (sb[g] >= thresh) {
            int pos = atomicAdd(&ccount, 1);
            if (pos < 1024) clist[pos] = g;
        }
    }
    __syncthreads();
    int nc = ccount; if (nc > 1024) nc = 1024;

    unsigned long long best = 0ull;
    for (int ci = wid; ci < nc; ci += 8) {
        int g = clist[ci];
#pragma unroll
        for (int r = 0; r < 8; r++) {
            int m = g * 8 + r;
            const float4* mr = (const float4*)(mem + (size_t)m * D);
            float s = 0.f;
#pragma unroll
            for (int i = 0; i < 4; i++) {
                float4 q = mr[lane + i * 32];
                float4 c = *(const float4*)&cs[(lane + i * 32) * 4];
                s = fmaf(q.x, c.x, s); s = fmaf(q.y, c.y, s);
                s = fmaf(q.z, c.z, s); s = fmaf(q.w, c.w, s);
            }
#pragma unroll
            for (int o = 16; o > 0; o >>= 1) s += __shfl_xor_sync(0xffffffffu, s, o);
            s *= g_inv_norm[m];
            unsigned long long key = ((unsigned long long)f2mono(s) << 32) |
                                     (unsigned long long)(0xFFFFFFFFu - (unsigned)m);
            if (key > best) best = key;
        }
    }
#pragma unroll
    for (int o = 16; o > 0; o >>= 1) {
        unsigned long long ok = __shfl_xor_sync(0xffffffffu, best, o);
        if (ok > best) best = ok;
    }
    if (lane == 0) wkey[wid] = best;
    __syncthreads();
    if (tid == 0) {
        unsigned long long k = wkey[0];
#pragma unroll
        for (int i = 1; i < 8; i++) if (wkey[i] > k) k = wkey[i];
        sbest = (int)(0xFFFFFFFFu - (unsigned)(k & 0xFFFFFFFFull));
    }
    __syncthreads();

    // fused gather: out[0, b, :] = memory[sbest, :]
    const int idx = sbest;
    const float4* src = (const float4*)(mem + (size_t)idx * D);
    float4* dst = (float4*)(out + (size_t)b * D);
    if (tid < D / 4) dst[tid] = src[tid];
}

// ---------------- launch ----------------
extern "C" void kernel_launch(void* const* d_in, const int* in_sizes, int n_in,
                              void* d_out, int out_size)
{
    const float* ctx = (const float*)d_in[0];   // [512, 512] f32
    const float* mem = (const float*)d_in[1];   // [65536, 512] f32
    float* out = (float*)d_out;                 // [1, 512, 512] f32

    cudaFuncSetAttribute(gemm_kernel, cudaFuncAttributeMaxDynamicSharedMemorySize, SMEM_DYN);

    convert_kernel<<<(NM + NB) / 8, 256>>>(mem, ctx);
    gemm_kernel<<<dim3(NB / BT, NTILES), 256, SMEM_DYN>>>();
    rescue_kernel<<<NB, 256>>>(ctx, mem, out);
}